// round 4
// baseline (speedup 1.0000x reference)
#include <cuda_runtime.h>

// ImageRotator: out[n][a][y][x] = bilinear sample of img[n] at the position
// (x,y) rotated by angles[a] about the image center, zero outside.
// img: (32, 1, 512, 512) fp32   angles: (8,) fp32 (degrees)
// out: (32, 8, 512, 512) fp32
//
// One thread per (a, y, x); coordinate/weight work shared across all 32 images.

#define IMG_H 512
#define IMG_W 512
#define N_IMG 32
#define N_ANG 8
#define HW (IMG_H * IMG_W)

__global__ __launch_bounds__(256) void rotate_kernel(
    const float* __restrict__ img,    // 32 * 512 * 512
    const float* __restrict__ angles, // 8
    float* __restrict__ out)          // 32 * 8 * 512 * 512
{
    int idx = blockIdx.x * blockDim.x + threadIdx.x;
    int x = idx & (IMG_W - 1);
    int y = (idx >> 9) & (IMG_H - 1);
    int a = idx >> 18;
    if (a >= N_ANG) return;

    float ang = angles[a] * 0.017453292519943295f;
    float sa, ca;
    sincosf(ang, &sa, &ca);   // sincosf(x, sin*, cos*): sin FIRST (this was the R1/R2 bug)

    const float cx = (IMG_W - 1) * 0.5f;
    const float cy = (IMG_H - 1) * 0.5f;
    float X = (float)x - cx;
    float Y = (float)y - cy;
    float sx = fmaf(ca, X, fmaf(-sa, Y, cx));   // ca*X - sa*Y + cx
    float sy = fmaf(sa, X, fmaf(ca, Y, cy));    // sa*X + ca*Y + cy

    float x0f = floorf(sx);
    float y0f = floorf(sy);
    float wx = sx - x0f;
    float wy = sy - y0f;

    int x0 = (int)x0f;
    int y0 = (int)y0f;
    int x1 = x0 + 1;
    int y1 = y0 + 1;

    bool vx0 = (x0 >= 0) & (x0 < IMG_W);
    bool vx1 = (x1 >= 0) & (x1 < IMG_W);
    bool vy0 = (y0 >= 0) & (y0 < IMG_H);
    bool vy1 = (y1 >= 0) & (y1 < IMG_H);

    int xc0 = min(max(x0, 0), IMG_W - 1);
    int xc1 = min(max(x1, 0), IMG_W - 1);
    int yc0 = min(max(y0, 0), IMG_H - 1);
    int yc1 = min(max(y1, 0), IMG_H - 1);

    float omwx = 1.0f - wx;
    float omwy = 1.0f - wy;

    // Fold validity into weights -> branch-free inner loop
    float w00 = (vy0 && vx0) ? (omwy * omwx) : 0.0f;
    float w01 = (vy0 && vx1) ? (omwy * wx)   : 0.0f;
    float w10 = (vy1 && vx0) ? (wy * omwx)   : 0.0f;
    float w11 = (vy1 && vx1) ? (wy * wx)     : 0.0f;

    int o00 = yc0 * IMG_W + xc0;
    int o01 = yc0 * IMG_W + xc1;
    int o10 = yc1 * IMG_W + xc0;
    int o11 = yc1 * IMG_W + xc1;

    const float* ip = img;
    float* op = out + ((size_t)a * IMG_H + (size_t)y) * IMG_W + (size_t)x;

#pragma unroll 4
    for (int n = 0; n < N_IMG; n++) {
        float v00 = __ldg(ip + o00);
        float v01 = __ldg(ip + o01);
        float v10 = __ldg(ip + o10);
        float v11 = __ldg(ip + o11);
        float v = fmaf(v00, w00, fmaf(v01, w01, fmaf(v10, w10, v11 * w11)));
        op[(size_t)n * (N_ANG * HW)] = v;
        ip += HW;
    }
}

extern "C" void kernel_launch(void* const* d_in, const int* in_sizes, int n_in,
                              void* d_out, int out_size) {
    // Resolve inputs by size — robust to metadata ordering.
    const float* img;
    const float* angles;
    if (in_sizes[0] > in_sizes[1]) {
        img    = (const float*)d_in[0];
        angles = (const float*)d_in[1];
    } else {
        angles = (const float*)d_in[0];
        img    = (const float*)d_in[1];
    }
    float* out = (float*)d_out;

    int total = N_ANG * IMG_H * IMG_W;        // 2,097,152 threads
    int block = 256;
    int grid = (total + block - 1) / block;   // 8192 blocks
    rotate_kernel<<<grid, block>>>(img, angles, out);
}

// round 5
// speedup vs baseline: 1.4515x; 1.4515x over previous
#include <cuda_runtime.h>

// ImageRotator, tiled-gather version.
// img: (32, 1, 512, 512) fp32   angles: (8,) fp32 (degrees)
// out: (32, 8, 512, 512) fp32
//
// Block = 256 threads = one (angle, 32x32 output tile); loops over the 32
// images with double-buffered smem source tiles. The rotated-gather (which
// exploded L1tex wavefronts in the naive kernel: up to ~46 lines per warp
// load) becomes an LDS from a 48x48(+pad) tile; gmem reads are coalesced.

#define IMG_H 512
#define IMG_W 512
#define N_IMG 32
#define N_ANG 8
#define HW (IMG_H * IMG_W)
#define TILE 32
#define BB 48           // source bbox buffer: 31*(|c|+|s|) <= 43.9, +2 taps +1 margin <= 47
#define BSTR 49         // padded row stride (odd -> reduced bank conflicts)
#define LOADS_PER_THREAD 9   // 48*48 / 256

__global__ __launch_bounds__(256) void rotate_tiled(
    const float* __restrict__ img,
    const float* __restrict__ angles,
    float* __restrict__ out)
{
    __shared__ float sbuf[2][BB * BSTR];

    const int a   = blockIdx.z;
    const int tx0 = blockIdx.x * TILE;
    const int ty0 = blockIdx.y * TILE;

    const float ang = angles[a] * 0.017453292519943295f;
    float sa, ca;
    sincosf(ang, &sa, &ca);   // sin FIRST
    const float cx = (IMG_W - 1) * 0.5f;
    const float cy = (IMG_H - 1) * 0.5f;

    // Source bbox of this tile. Same fmaf expression as the per-pixel path so
    // corner extrema bound the interior samples; -1 margin for ULP safety.
    const float Xa = (float)tx0 - cx,  Xb = (float)(tx0 + TILE - 1) - cx;
    const float Ya = (float)ty0 - cy,  Yb = (float)(ty0 + TILE - 1) - cy;
    float sxa0 = fmaf(ca, Xa, fmaf(-sa, Ya, cx));
    float sxa1 = fmaf(ca, Xb, fmaf(-sa, Ya, cx));
    float sxa2 = fmaf(ca, Xa, fmaf(-sa, Yb, cx));
    float sxa3 = fmaf(ca, Xb, fmaf(-sa, Yb, cx));
    float sya0 = fmaf(sa, Xa, fmaf(ca, Ya, cy));
    float sya1 = fmaf(sa, Xb, fmaf(ca, Ya, cy));
    float sya2 = fmaf(sa, Xa, fmaf(ca, Yb, cy));
    float sya3 = fmaf(sa, Xb, fmaf(ca, Yb, cy));
    const int bx0 = (int)floorf(fminf(fminf(sxa0, sxa1), fminf(sxa2, sxa3))) - 1;
    const int by0 = (int)floorf(fminf(fminf(sya0, sya1), fminf(sya2, sya3))) - 1;

    const int tid  = threadIdx.x;
    const int orow = tid >> 3;          // 0..31
    const int ocol = (tid & 7) << 2;    // 0,4,...,28 (4 consecutive x per thread)
    const int oy   = ty0 + orow;
    const float Yf = (float)oy - cy;

    // ---- n-invariant precompute: weights + smem offsets for 4 outputs ----
    int   offs[4][4];
    float wts[4][4];
#pragma unroll
    for (int j = 0; j < 4; j++) {
        int ox = tx0 + ocol + j;
        float Xf = (float)ox - cx;
        float sx = fmaf(ca, Xf, fmaf(-sa, Yf, cx));
        float sy = fmaf(sa, Xf, fmaf(ca, Yf, cy));
        float x0f = floorf(sx), y0f = floorf(sy);
        float wx = sx - x0f,   wy = sy - y0f;
        int x0 = (int)x0f, y0 = (int)y0f;
        int x1 = x0 + 1,   y1 = y0 + 1;
        bool vx0 = (x0 >= 0) & (x0 < IMG_W);
        bool vx1 = (x1 >= 0) & (x1 < IMG_W);
        bool vy0 = (y0 >= 0) & (y0 < IMG_H);
        bool vy1 = (y1 >= 0) & (y1 < IMG_H);
        int xc0 = min(max(x0, 0), IMG_W - 1), xc1 = min(max(x1, 0), IMG_W - 1);
        int yc0 = min(max(y0, 0), IMG_H - 1), yc1 = min(max(y1, 0), IMG_H - 1);
        float omwx = 1.0f - wx, omwy = 1.0f - wy;
        wts[j][0] = (vy0 && vx0) ? (omwy * omwx) : 0.0f;
        wts[j][1] = (vy0 && vx1) ? (omwy * wx)   : 0.0f;
        wts[j][2] = (vy1 && vx0) ? (wy * omwx)   : 0.0f;
        wts[j][3] = (vy1 && vx1) ? (wy * wx)     : 0.0f;
        // local indices; clamped into the buffer as a hard safety net
        int xi0 = min(max(xc0 - bx0, 0), BB - 1), xi1 = min(max(xc1 - bx0, 0), BB - 1);
        int yi0 = min(max(yc0 - by0, 0), BB - 1), yi1 = min(max(yc1 - by0, 0), BB - 1);
        offs[j][0] = yi0 * BSTR + xi0;
        offs[j][1] = yi0 * BSTR + xi1;
        offs[j][2] = yi1 * BSTR + xi0;
        offs[j][3] = yi1 * BSTR + xi1;
    }

    // ---- n-invariant load addresses (clamped; border duplication is fine) ----
    int laddr[LOADS_PER_THREAD];
    int lidx[LOADS_PER_THREAD];
#pragma unroll
    for (int k = 0; k < LOADS_PER_THREAD; k++) {
        int i = tid + k * 256;          // 0..2303
        int r = i / BB;
        int c = i - r * BB;
        int gy = min(max(by0 + r, 0), IMG_H - 1);
        int gx = min(max(bx0 + c, 0), IMG_W - 1);
        laddr[k] = gy * IMG_W + gx;
        lidx[k]  = r * BSTR + c;
    }

    // ---- prologue: fill buffer 0 with image 0 ----
#pragma unroll
    for (int k = 0; k < LOADS_PER_THREAD; k++)
        sbuf[0][lidx[k]] = __ldg(img + laddr[k]);
    __syncthreads();

    float* op = out + ((size_t)a * IMG_H + (size_t)oy) * IMG_W + (tx0 + ocol);

    for (int n = 0; n < N_IMG; n++) {
        const float* sb = sbuf[n & 1];
        if (n + 1 < N_IMG) {
            const float* ipn = img + (size_t)(n + 1) * HW;
            float* db = sbuf[(n + 1) & 1];
#pragma unroll
            for (int k = 0; k < LOADS_PER_THREAD; k++)
                db[lidx[k]] = __ldg(ipn + laddr[k]);
        }

        float acc[4];
#pragma unroll
        for (int j = 0; j < 4; j++) {
            float v00 = sb[offs[j][0]];
            float v01 = sb[offs[j][1]];
            float v10 = sb[offs[j][2]];
            float v11 = sb[offs[j][3]];
            acc[j] = fmaf(v00, wts[j][0],
                     fmaf(v01, wts[j][1],
                     fmaf(v10, wts[j][2], v11 * wts[j][3])));
        }
        *(float4*)op = make_float4(acc[0], acc[1], acc[2], acc[3]);
        op += (size_t)N_ANG * HW;

        __syncthreads();   // buffer rotation barrier
    }
}

extern "C" void kernel_launch(void* const* d_in, const int* in_sizes, int n_in,
                              void* d_out, int out_size) {
    const float* img;
    const float* angles;
    if (in_sizes[0] > in_sizes[1]) {
        img    = (const float*)d_in[0];
        angles = (const float*)d_in[1];
    } else {
        angles = (const float*)d_in[0];
        img    = (const float*)d_in[1];
    }
    float* out = (float*)d_out;

    dim3 grid(IMG_W / TILE, IMG_H / TILE, N_ANG);   // (16, 16, 8)
    rotate_tiled<<<grid, 256>>>(img, angles, out);
}